// round 3
// baseline (speedup 1.0000x reference)
#include <cuda_runtime.h>

// spixel_upsample2d: out[b, 4h+a, 4w+d] = sum_{c<2, ky<3, kx<3}
//     cv[b, c, h+ky-1, w+kx-1] * sp[b, c*9 + ky*3+kx, 4h+a, 4w+d]
// cv: (4,2,128,256) fp32, sp: (4,18,512,1024) fp32, out: (4,1,512,1024) fp32.
// HBM-bound: one streaming pass over sp (151 MB) + 8.4 MB out write.
// One thread = one (b, y, w) owning the float4 of subpixel columns d=0..3.

#define BB 4
#define CC 2
#define HH 128
#define WW 256
#define H4 512
#define W4 1024

__global__ __launch_bounds__(256, 4)
void spixel_up_kernel(const float* __restrict__ cv,
                      const float* __restrict__ sp,
                      float* __restrict__ out) {
    const int w  = threadIdx.x;            // 0..255  (coarse column)
    const int by = blockIdx.x;             // 0..2047 = b*512 + y
    const int y  = by & (H4 - 1);          // output row 0..511
    const int b  = by >> 9;                // batch
    const int h  = y >> 2;                 // coarse row

    // ---- 18 patch values (invariant across the 4 subpixel columns) ----
    float p[CC][9];
#pragma unroll
    for (int c = 0; c < CC; c++) {
        const float* __restrict__ xb = cv + ((size_t)(b * CC + c) * HH) * WW;
#pragma unroll
        for (int ky = 0; ky < 3; ky++) {
            const int hh = h + ky - 1;
            const bool hv = (hh >= 0) && (hh < HH);
#pragma unroll
            for (int kx = 0; kx < 3; kx++) {
                const int wwc = w + kx - 1;
                const bool v = hv && (wwc >= 0) && (wwc < WW);
                p[c][ky * 3 + kx] = v ? xb[(size_t)hh * WW + wwc] : 0.0f;
            }
        }
    }

    // ---- 18 independent float4 streams from sp, accumulate ----
    // sp element index: ((b*18 + (c*9+k))*H4 + y)*W4 + 4*w
    const float4* __restrict__ spb =
        reinterpret_cast<const float4*>(sp + ((size_t)b * 18 * H4 + (size_t)y) * W4) + w;
    const size_t ch_stride4 = (size_t)H4 * W4 / 4;   // 131072 float4 per channel

    float4 acc = make_float4(0.f, 0.f, 0.f, 0.f);
#pragma unroll
    for (int c = 0; c < CC; c++) {
#pragma unroll
        for (int k = 0; k < 9; k++) {
            const float4 s = spb[(size_t)(c * 9 + k) * ch_stride4];
            const float v = p[c][k];
            acc.x = fmaf(v, s.x, acc.x);
            acc.y = fmaf(v, s.y, acc.y);
            acc.z = fmaf(v, s.z, acc.z);
            acc.w = fmaf(v, s.w, acc.w);
        }
    }

    reinterpret_cast<float4*>(out + ((size_t)b * H4 + y) * W4)[w] = acc;
}

extern "C" void kernel_launch(void* const* d_in, const int* in_sizes, int n_in,
                              void* d_out, int out_size) {
    // Bind inputs by element count (robust to metadata ordering).
    const int CV_N = BB * CC * HH * WW;          // 262144
    const float* cv = nullptr;
    const float* sp = nullptr;
    for (int i = 0; i < n_in; i++) {
        if (in_sizes[i] == CV_N) cv = (const float*)d_in[i];
        else                     sp = (const float*)d_in[i];
    }
    float* out = (float*)d_out;

    dim3 grid(BB * H4);      // 2048 blocks, one per (b, output row)
    dim3 block(256);         // one thread per coarse column (float4 of output)
    spixel_up_kernel<<<grid, block>>>(cv, sp, out);
}

// round 4
// speedup vs baseline: 1.0718x; 1.0718x over previous
#include <cuda_runtime.h>

// spixel_upsample2d: out[b, 4h+a, 4w+d] = sum_{c<2, ky<3, kx<3}
//     cv[b, c, h+ky-1, w+kx-1] * sp[b, c*9 + ky*3+kx, 4h+a, 4w+d]
// cv: (4,2,128,256) fp32 (1 MB, L2-resident, reused 144x)
// sp: (4,18,512,1024) fp32 (151 MB, streamed once)  out: (4,1,512,1024) fp32 (8.4 MB)
// HBM-bound. One thread = one (b, y, w) float4 of subpixel columns.
// R3: half-row blocks (finer tail drain) + streaming cache hints on sp/out.

#define BB 4
#define CC 2
#define HH 128
#define WW 256
#define H4 512
#define W4 1024

__global__ __launch_bounds__(128, 8)
void spixel_up_kernel(const float* __restrict__ cv,
                      const float* __restrict__ sp,
                      float* __restrict__ out) {
    const int bid  = blockIdx.x;                 // 0..4095
    const int half = bid & 1;                    // which half-row
    const int y    = (bid >> 1) & (H4 - 1);      // output row 0..511
    const int b    = bid >> 10;                  // batch
    const int w    = half * 128 + threadIdx.x;   // coarse column 0..255
    const int h    = y >> 2;                     // coarse row

    // ---- 18 patch values (invariant across the 4 subpixel columns) ----
    // cv is tiny and heavily reused -> default (caching) loads.
    float p[CC][9];
#pragma unroll
    for (int c = 0; c < CC; c++) {
        const float* __restrict__ xb = cv + ((size_t)(b * CC + c) * HH) * WW;
#pragma unroll
        for (int ky = 0; ky < 3; ky++) {
            const int hh = h + ky - 1;
            const bool hv = (hh >= 0) && (hh < HH);
#pragma unroll
            for (int kx = 0; kx < 3; kx++) {
                const int wwc = w + kx - 1;
                const bool v = hv && (wwc >= 0) && (wwc < WW);
                p[c][ky * 3 + kx] = v ? __ldg(&xb[(size_t)hh * WW + wwc]) : 0.0f;
            }
        }
    }

    // ---- 18 independent float4 streaming loads from sp, accumulate ----
    const float4* __restrict__ spb =
        reinterpret_cast<const float4*>(sp + ((size_t)b * 18 * H4 + (size_t)y) * W4) + w;
    const size_t ch_stride4 = (size_t)H4 * W4 / 4;   // 131072 float4 per channel

    float4 acc = make_float4(0.f, 0.f, 0.f, 0.f);
#pragma unroll
    for (int c = 0; c < CC; c++) {
#pragma unroll
        for (int k = 0; k < 9; k++) {
            const float4 s = __ldcs(&spb[(size_t)(c * 9 + k) * ch_stride4]);  // evict-first
            const float v = p[c][k];
            acc.x = fmaf(v, s.x, acc.x);
            acc.y = fmaf(v, s.y, acc.y);
            acc.z = fmaf(v, s.z, acc.z);
            acc.w = fmaf(v, s.w, acc.w);
        }
    }

    __stcs(&reinterpret_cast<float4*>(out + ((size_t)b * H4 + y) * W4)[w], acc);
}

extern "C" void kernel_launch(void* const* d_in, const int* in_sizes, int n_in,
                              void* d_out, int out_size) {
    // Bind inputs by element count (robust to metadata ordering).
    const int CV_N = BB * CC * HH * WW;          // 262144
    const float* cv = nullptr;
    const float* sp = nullptr;
    for (int i = 0; i < n_in; i++) {
        if (in_sizes[i] == CV_N) cv = (const float*)d_in[i];
        else                     sp = (const float*)d_in[i];
    }
    float* out = (float*)d_out;

    dim3 grid(BB * H4 * 2);   // 4096 blocks: one per (b, row, half-row)
    dim3 block(128);          // one thread per coarse column in the half-row
    spixel_up_kernel<<<grid, block>>>(cv, sp, out);
}